// round 15
// baseline (speedup 1.0000x reference)
#include <cuda_runtime.h>
#include <math.h>

#define BB 128
#define TT 512
#define II 256
#define HH 512
#define NTH 512            // scan: 16 warps
#define PNTH 256           // pre kernel threads
#define PK  516            // sH row pitch (floats)

typedef unsigned long long ull;

// ---------------------------------------------------------------------------
// Scratch (no cudaMalloc allowed)
// ---------------------------------------------------------------------------
__device__ float g_pre[(size_t)TT * 3 * BB * HH];   // [t][gate][b][h]
__device__ float g_h [BB * HH];
__device__ float g_z [BB * HH];
__device__ float g_rh[BB * HH];
__device__ unsigned int g_bars[8 * 32];             // 8 group counters, 128B apart
__device__ unsigned int g_done = 0;

// Packed fp32x2 FMA (SASS FFMA2) — PTX-only.
__device__ __forceinline__ void ffma2(ull& d, ull a, ull b) {
    asm("fma.rn.f32x2 %0, %1, %2, %0;" : "+l"(d) : "l"(a), "l"(b));
}
__device__ __forceinline__ float pair_sum(ull v) {
    return __uint_as_float((unsigned)v) + __uint_as_float((unsigned)(v >> 32));
}
__device__ __forceinline__ float fsig(float v) {
    return 1.0f / (1.0f + __expf(-v));
}

// Release/acquire group barrier (no gpu-scope fence: CCTL.IVALL would flush L1)
__device__ __forceinline__ unsigned atom_add_release(unsigned int* p, unsigned int v) {
    unsigned int old;
    asm volatile("atom.release.gpu.add.u32 %0, [%1], %2;"
                 : "=r"(old) : "l"(p), "r"(v) : "memory");
    return old;
}
__device__ __forceinline__ unsigned ld_acquire(unsigned int* p) {
    unsigned int v;
    asm volatile("ld.acquire.gpu.u32 %0, [%1];" : "=r"(v) : "l"(p) : "memory");
    return v;
}
__device__ __forceinline__ void group_sync(unsigned int* bar, unsigned int goal) {
    __syncthreads();
    if (threadIdx.x == 0) {
        atom_add_release(bar, 1u);
        while (ld_acquire(bar) < goal) { }
    }
    __syncthreads();
}

// ---------------------------------------------------------------------------
// Precompute: pre[t][g][b][h] = dot(x[b,t,:], w_g[h,:]) + (w_bg + r_bg)
// f32x2, smem in k-pair (ull) layout, 8x4 microtile, 2 CTAs/SM. (R13/R14-proven)
// ---------------------------------------------------------------------------
#define PA 260
#define PB 132

__global__ void __launch_bounds__(PNTH, 2)
gru_pre_kernel(const float* __restrict__ x,
               const float* __restrict__ w_z, const float* __restrict__ w_r,
               const float* __restrict__ w_h,
               const float* __restrict__ w_bz, const float* __restrict__ w_br,
               const float* __restrict__ w_bh,
               const float* __restrict__ r_bz, const float* __restrict__ r_br,
               const float* __restrict__ r_bh)
{
    __shared__ __align__(16) float sA2[8 * PA];
    __shared__ __align__(16) float sB2[8 * PB];

    const int tid  = threadIdx.x;
    const int m0   = blockIdx.y * 128;
    const int n0   = blockIdx.x * 64;
    const int gate = n0 >> 9;
    const int hb   = n0 & (HH - 1);

    const float* W  = (gate == 0) ? w_z  : ((gate == 1) ? w_r  : w_h);
    const float* wb = (gate == 0) ? w_bz : ((gate == 1) ? w_br : w_bh);
    const float* rb = (gate == 0) ? r_bz : ((gate == 1) ? r_br : r_bh);

    const int lr  = tid & 63;
    const int lk  = (tid >> 6) << 2;
    const int k2b = lk >> 1;
    const int ty  = tid >> 4;
    const int tx  = tid & 15;

    ull acc[8][4];
#pragma unroll
    for (int i = 0; i < 8; i++)
#pragma unroll
        for (int j = 0; j < 4; j++) acc[i][j] = 0ull;

    const float* xA0 = x + (size_t)(m0 + lr)      * II + lk;
    const float* xA1 = x + (size_t)(m0 + lr + 64) * II + lk;
    const float* wB  = W + (size_t)(hb + lr)      * II + lk;

    float4 a0 = *(const float4*)(xA0);
    float4 a1 = *(const float4*)(xA1);
    float4 b0 = *(const float4*)(wB);

    for (int k0 = 0; k0 < II; k0 += 16) {
        __syncthreads();
        *(float2*)(sA2 + (k2b+0)*PA + 2*lr)        = make_float2(a0.x, a0.y);
        *(float2*)(sA2 + (k2b+1)*PA + 2*lr)        = make_float2(a0.z, a0.w);
        *(float2*)(sA2 + (k2b+0)*PA + 2*(lr + 64)) = make_float2(a1.x, a1.y);
        *(float2*)(sA2 + (k2b+1)*PA + 2*(lr + 64)) = make_float2(a1.z, a1.w);
        *(float2*)(sB2 + (k2b+0)*PB + 2*lr)        = make_float2(b0.x, b0.y);
        *(float2*)(sB2 + (k2b+1)*PB + 2*lr)        = make_float2(b0.z, b0.w);
        __syncthreads();
        if (k0 + 16 < II) {
            a0 = *(const float4*)(xA0 + k0 + 16);
            a1 = *(const float4*)(xA1 + k0 + 16);
            b0 = *(const float4*)(wB  + k0 + 16);
        }
#pragma unroll
        for (int k2 = 0; k2 < 8; k2++) {
            ulonglong2 a01 = *(const ulonglong2*)(sA2 + k2*PA + 8*ty);
            ulonglong2 a23 = *(const ulonglong2*)(sA2 + k2*PA + 8*ty + 4);
            ulonglong2 a45 = *(const ulonglong2*)(sA2 + k2*PA + 8*ty + 128);
            ulonglong2 a67 = *(const ulonglong2*)(sA2 + k2*PA + 8*ty + 132);
            ulonglong2 b01 = *(const ulonglong2*)(sB2 + k2*PB + 8*tx);
            ulonglong2 b23 = *(const ulonglong2*)(sB2 + k2*PB + 8*tx + 4);
            ull a[8] = {a01.x, a01.y, a23.x, a23.y, a45.x, a45.y, a67.x, a67.y};
            ull b[4] = {b01.x, b01.y, b23.x, b23.y};
#pragma unroll
            for (int i = 0; i < 8; i++)
#pragma unroll
                for (int j = 0; j < 4; j++)
                    ffma2(acc[i][j], a[i], b[j]);
        }
    }

    const int hcol = hb + 4*tx;
    float bias[4];
#pragma unroll
    for (int j = 0; j < 4; j++) bias[j] = wb[hcol + j] + rb[hcol + j];

#pragma unroll
    for (int i = 0; i < 8; i++) {
        int row = (i < 4) ? (4*ty + i) : (64 + 4*ty + (i - 4));
        int m = m0 + row;
        int b = m >> 9;
        int t = m & (TT - 1);
        size_t base = ((size_t)((t*3 + gate) * BB + b)) * HH + hcol;
        *(float4*)(g_pre + base) =
            make_float4(pair_sum(acc[i][0]) + bias[0], pair_sum(acc[i][1]) + bias[1],
                        pair_sum(acc[i][2]) + bias[2], pair_sum(acc[i][3]) + bias[3]);
    }
}

// ---------------------------------------------------------------------------
// Persistent scan — R15: 8 groups of 16 CTAs / 16 batch rows, 512 threads
// (16 warps = 4/SMSP for latency hiding). Weights in smem, loaded once.
//  ph1 (16r x 64c): warp = 4r x 16c (4 rg x 4 cg), thread = 1r x 2c.
//      per k4: 3 LDS (hv 64B, w0/w1 128B) per 4 FFMA2; even/odd-k accums.
//  ph2 (16r x 32c): warp = 4r x 8c, thread = 1r x 1c.
//      sW2 layout [k4][col][4] -> ONE LDS.128 per thread per k4, 2 FFMA2.
// smem: sW1 128KB | sW2 64KB | sH 33KB = 229.6KB.
// ---------------------------------------------------------------------------
#define SW1_F (256 * 128)                  // [k2][2*j], j 0..63
#define SW2_F (128 * 128)                  // [k4][j][4], j 0..31
#define SMEM_SH (SW1_F + SW2_F)
#define SCAN_SMEM_BYTES ((SW1_F + SW2_F + 16 * PK) * 4)   // 229,632 B

__device__ __forceinline__ void stage16x512(const float* __restrict__ src,
                                            float* sH, int b0t, int tid) {
#pragma unroll
    for (int i = 0; i < 4; i++) {
        int idx = i * NTH + tid;            // 0..2047
        int row = idx >> 7, k4 = idx & 127;
        float4 v = __ldcg((const float4*)(src + (size_t)(b0t + row) * HH + 4 * k4));
        *(float4*)(sH + row * PK + 4 * k4) = v;
    }
}

__global__ void __launch_bounds__(NTH, 1)
gru_scan_kernel(const float* __restrict__ h0,
                const float* __restrict__ r_z, const float* __restrict__ r_r,
                const float* __restrict__ r_h,
                float* __restrict__ out, int write_hlast)
{
    extern __shared__ __align__(16) float sm[];
    float* sW1 = sm;                 // [k2][2*j], j 0..63
    float* sW2 = sm + SW1_F;         // [k4][j][4], j 0..31
    float* sH  = sm + SMEM_SH;       // [row][PK], 16 rows

    const int tid  = threadIdx.x;
    const int bid  = blockIdx.x;
    const int lane = tid & 31;
    const int w    = tid >> 5;           // 0..15
    const int mt   = bid >> 4;           // group 0..7
    const int nt   = bid & 15;           // CTA in group
    const int b0t   = mt * 16;
    const int p2_j0 = nt * 32;
    const int gate  = (nt < 8) ? 0 : 1;
    const int jj0   = (nt & 7) * 64;     // gate-local ph1 col base

    unsigned int* bar = &g_bars[mt * 32];
    const float* Rzr = gate ? r_r : r_z;

    // ---- load persistent weight tiles into smem ----
#pragma unroll
    for (int i = 0; i < 16; i++) {
        int idx = i * NTH + tid;            // 0..8191
        int j = idx >> 7, k4 = idx & 127;   // j 0..63
        float4 v = *(const float4*)(Rzr + (size_t)(jj0 + j) * HH + 4 * k4);
        *(float2*)(sW1 + (2*k4)   * 128 + 2*j) = make_float2(v.x, v.y);
        *(float2*)(sW1 + (2*k4+1) * 128 + 2*j) = make_float2(v.z, v.w);
    }
#pragma unroll
    for (int i = 0; i < 8; i++) {
        int idx = i * NTH + tid;            // 0..4095
        int j = idx >> 7, k4 = idx & 127;   // j 0..31
        float4 v = *(const float4*)(r_h + (size_t)(p2_j0 + j) * HH + 4 * k4);
        *(float4*)(sW2 + k4 * 128 + j * 4) = v;
    }

    // ---- phase-1 mapping: warp = 4r x 16c (rg = w&3, cg = w>>2) ----
    const int r1 = (w & 3) * 4 + (lane >> 3);        // 0..15
    const int c1 = (w >> 2) * 16 + 2 * (lane & 7);   // 0..62 even

    // ---- phase-2 mapping: warp = 4r x 8c (rg2 = w&3, cg2 = w>>2) ----
    const int r2 = (w & 3) * 4 + (lane >> 3);        // 0..15
    const int c2 = (w >> 2) * 8 + (lane & 7);        // 0..31

    // ---- init h state ----
    g_h[bid * 512 + tid] = h0[bid * 512 + tid];      // CTA bid owns g_h row bid
    const int grow2 = b0t + r2;
    const int gj2   = p2_j0 + c2;
    float hreg = h0[(size_t)grow2 * HH + gj2];

    unsigned int nbar = 0;
    group_sync(bar, ++nbar * 16);

    const float* hp1 = sH + r1 * PK;
    const float* wp1 = sW1 + 2 * c1;
    const float* hp2 = sH + r2 * PK;
    const float* wp2 = sW2 + 4 * c2;

    const int row1 = b0t + r1;
    const int col1 = jj0 + c1;

    for (int t = 0; t < TT; t++) {
        // ================= phase 1: z / r gates =================
        const float* pre1 = g_pre + (size_t)(t*3 + gate) * BB * HH;
        float2 pv = __ldcg((const float2*)(pre1 + (size_t)row1 * HH + col1));

        stage16x512(g_h, sH, b0t, tid);
        __syncthreads();
        {
            // even/odd k accumulators (no serial FFMA2 chains)
            ull a0e = 0ull, a0o = 0ull, a1e = 0ull, a1o = 0ull;
#pragma unroll 8
            for (int k4 = 0; k4 < 128; k4++) {
                ulonglong2 hv = *(const ulonglong2*)(hp1 + 4 * k4);
                ulonglong2 w0 = *(const ulonglong2*)(wp1 + (2*k4)   * 128);
                ulonglong2 w1 = *(const ulonglong2*)(wp1 + (2*k4+1) * 128);
                ffma2(a0e, hv.x, w0.x); ffma2(a1e, hv.x, w0.y);
                ffma2(a0o, hv.y, w1.x); ffma2(a1o, hv.y, w1.y);
            }
            float v0 = fsig(pair_sum(a0e) + pair_sum(a0o) + pv.x);
            float v1 = fsig(pair_sum(a1e) + pair_sum(a1o) + pv.y);
            if (gate == 0) {
                *(float2*)(g_z + (size_t)row1 * HH + col1) = make_float2(v0, v1);
            } else {
                float2 hv = *(const float2*)(hp1 + col1);    // h at (row1, col1)
                *(float2*)(g_rh + (size_t)row1 * HH + col1) =
                    make_float2(v0 * hv.x, v1 * hv.y);
            }
        }
        group_sync(bar, ++nbar * 16);

        // ================= phase 2: candidate + update =================
        const float* pre2 = g_pre + (size_t)(t*3 + 2) * BB * HH;
        float pz = __ldcg(pre2 + (size_t)grow2 * HH + gj2);
        float z  = __ldcg(g_z + (size_t)grow2 * HH + gj2);

        stage16x512(g_rh, sH, b0t, tid);
        __syncthreads();
        {
            ull ae = 0ull, ao = 0ull;
#pragma unroll 8
            for (int k4 = 0; k4 < 128; k4++) {
                ulonglong2 hv = *(const ulonglong2*)(hp2 + 4 * k4);
                ulonglong2 wv = *(const ulonglong2*)(wp2 + k4 * 128);
                ffma2(ae, hv.x, wv.x);
                ffma2(ao, hv.y, wv.y);
            }
            float hh = tanhf(pair_sum(ae) + pair_sum(ao) + pz);
            float hn = (1.0f - z) * hh + z * hreg;
            hreg = hn;
            g_h[(size_t)grow2 * HH + gj2] = hn;
            out[((size_t)grow2 * TT + t) * HH + gj2] = hn;
            if (write_hlast && t == TT - 1)
                out[(size_t)BB*TT*HH + (size_t)grow2 * HH + gj2] = hn;
        }
        group_sync(bar, ++nbar * 16);
    }

    // Reset barrier state for the next graph replay (last CTA overall).
    __syncthreads();
    if (tid == 0) {
        unsigned int old = atom_add_release(&g_done, 1u);
        if (old == BB - 1) {
#pragma unroll
            for (int g = 0; g < 8; g++) g_bars[g * 32] = 0;
            g_done = 0;
            __threadfence();
        }
    }
}

// ---------------------------------------------------------------------------
extern "C" void kernel_launch(void* const* d_in, const int* in_sizes, int n_in,
                              void* d_out, int out_size)
{
    const float* x    = (const float*)d_in[0];
    const float* h0   = (const float*)d_in[1];
    const float* w_z  = (const float*)d_in[2];
    const float* w_r  = (const float*)d_in[3];
    const float* w_h  = (const float*)d_in[4];
    const float* r_z  = (const float*)d_in[5];
    const float* r_r  = (const float*)d_in[6];
    const float* r_h  = (const float*)d_in[7];
    const float* w_bz = (const float*)d_in[8];
    const float* w_br = (const float*)d_in[9];
    const float* w_bh = (const float*)d_in[10];
    const float* r_bz = (const float*)d_in[11];
    const float* r_br = (const float*)d_in[12];
    const float* r_bh = (const float*)d_in[13];
    float* out = (float*)d_out;

    (void)in_sizes; (void)n_in;

    cudaFuncSetAttribute(gru_scan_kernel,
                         cudaFuncAttributeMaxDynamicSharedMemorySize,
                         SCAN_SMEM_BYTES);

    dim3 gpre(1536 / 64, (BB * TT) / 128);
    gru_pre_kernel<<<gpre, PNTH>>>(x, w_z, w_r, w_h,
                                   w_bz, w_br, w_bh, r_bz, r_br, r_bh);

    int write_hlast = (out_size >= (int)(BB * TT * HH + BB * HH)) ? 1 : 0;
    gru_scan_kernel<<<BB, NTH, SCAN_SMEM_BYTES>>>(h0, r_z, r_r, r_h, out, write_hlast);
}